// round 10
// baseline (speedup 1.0000x reference)
#include <cuda_runtime.h>
#include <cuda_fp16.h>
#include <math.h>
#include <stdint.h>

#define B_SZ   8
#define C_IN   64
#define HID    256
#define H_SZ   256
#define W_SZ   256
#define THREADS 256
#define NH     64           // hid chunk
#define NCHUNK 4

// common pitch: 64 halfs = 128B data + 16 pad = 144 B (9 x 16B, ldmatrix clean)
#define PB 144

// ---------------- smem layout (bytes) ----------------
#define X_OFF    0          // 128 x 144 = 18432
#define H_OFF    18432      // 128 x 144 = 18432
#define W1_OFF   36864      // 2 bufs x (64 x 144 = 9216)
#define W2_OFF   55296      // 2 bufs x 9216
#define B1S_OFF  73728      // 256 f32
#define B2S_OFF  74752      // 64 f32
#define SMEM_BYTES 75008

// final-stage overlay (X+H dead after loop): 64 x 132 f32 = 33792
#define YS_OFF  0
#define X_PITCH 132

// ---------------------------------------------------------------------------
__device__ __forceinline__ uint32_t smem_u32(const void* p) {
    uint32_t a;
    asm("{ .reg .u64 t; cvta.to.shared.u64 t, %1; cvt.u32.u64 %0, t; }" : "=r"(a) : "l"(p));
    return a;
}

#define LDSM4(r0, r1, r2, r3, addr) \
    asm volatile("ldmatrix.sync.aligned.m8n8.x4.shared.b16 {%0,%1,%2,%3}, [%4];" \
        : "=r"(r0), "=r"(r1), "=r"(r2), "=r"(r3) : "r"(addr))

__device__ __forceinline__ void mma16816(float* d, const uint32_t* a, const uint32_t* b) {
    asm volatile(
        "mma.sync.aligned.m16n8k16.row.col.f32.f16.f16.f32 "
        "{%0,%1,%2,%3}, {%4,%5,%6,%7}, {%8,%9}, {%0,%1,%2,%3};"
        : "+f"(d[0]), "+f"(d[1]), "+f"(d[2]), "+f"(d[3])
        : "r"(a[0]), "r"(a[1]), "r"(a[2]), "r"(a[3]), "r"(b[0]), "r"(b[1]));
}

__device__ __forceinline__ void cp16(uint32_t dst, const void* src) {
    asm volatile("cp.async.cg.shared.global [%0], [%1], 16;"
                 :: "r"(dst), "l"(__cvta_generic_to_global(src)) : "memory");
}
__device__ __forceinline__ void cp_commit() {
    asm volatile("cp.async.commit_group;" ::: "memory");
}
template <int N>
__device__ __forceinline__ void cp_wait() {
    asm volatile("cp.async.wait_group %0;" :: "n"(N) : "memory");
}

__device__ __forceinline__ uint32_t ph2(__half a, __half b) {
    uint32_t r;
    asm("mov.b32 %0, {%1, %2};" : "=r"(r)
        : "h"(__half_as_ushort(a)), "h"(__half_as_ushort(b)));
    return r;
}

__device__ __forceinline__ float gelu_exact(float x) {
    return 0.5f * x * (1.f + erff(x * 0.70710678118654752440f));
}

// ---------------------------------------------------------------------------
// Precomputed global scratch
// ---------------------------------------------------------------------------
__device__ float g_M[64 * 256];
__device__ __half g_w1h[HID * C_IN];
__device__ __half g_w2h[C_IN * HID];

__global__ void build_mix_kernel(const float* __restrict__ cw) {
    const int c   = blockIdx.x;
    const int t   = threadIdx.x;
    const int in  = t >> 4;
    const int out = t & 15;
    const int s  = in >> 2, tt = in & 3;
    const int p  = out >> 2, q  = out & 3;
    const float cs[4] = {1.f, 0.f, -1.f, 0.f};
    const float sn[4] = {0.f, 1.f, 0.f, -1.f};
    float tre[3] = {0.f, 0.f, 0.f};
    float tim[3] = {0.f, 0.f, 0.f};
    #pragma unroll
    for (int u = 0; u < 4; ++u) {
        const int e2 = (u * p) & 3;
        const float c2 = cs[e2], s2 = sn[e2];
        #pragma unroll
        for (int v = 0; v < 3; ++v) {
            const int e1 = (4 - ((u * s + v * tt) & 3)) & 3;
            const float yr = 0.25f * cs[e1];
            const float yi = 0.25f * sn[e1];
            const float wr = cw[((u * 3 + v) * 64 + c) * 2 + 0];
            const float wi = cw[((u * 3 + v) * 64 + c) * 2 + 1];
            const float zr = yr * wr - yi * wi;
            const float zi = yr * wi + yi * wr;
            tre[v] += zr * c2 - zi * s2;
            tim[v] += zr * s2 + zi * c2;
        }
    }
    const float sgn = (q & 1) ? -1.f : 1.f;
    g_M[c * 256 + out * 16 + in] =
        0.25f * (tre[0] + sgn * tre[2] + 2.f * (tre[1] * cs[q] - tim[1] * sn[q]));
}

__global__ void build_weights_kernel(const float* __restrict__ w1,
                                     const float* __restrict__ w2) {
    const int i = blockIdx.x * blockDim.x + threadIdx.x;   // 0..32767
    if (i < HID * C_IN) {
        g_w1h[i] = __float2half_rn(w1[i]);
    } else {
        const int j = i - HID * C_IN;
        g_w2h[j] = __float2half_rn(w2[j]);
    }
}

// ---------------------------------------------------------------------------
// Main kernel: fp16 hi-only, chunk-64, double-buffered weights, occ 3
// ---------------------------------------------------------------------------
__global__ __launch_bounds__(THREADS, 3)
void fmffn_kernel(const float* __restrict__ x,
                  const float* __restrict__ b1,
                  const float* __restrict__ b2,
                  float* __restrict__ out) {
    extern __shared__ char smem[];
    const uint32_t sb = smem_u32(smem);

    const int tid  = threadIdx.x;
    const int wid  = tid >> 5;
    const int lane = tid & 31;
    const int b    = blockIdx.z;
    const int h0   = blockIdx.y * 4;
    const int w0   = blockIdx.x * 32;

    float* b1_s = (float*)(smem + B1S_OFF);
    float* b2_s = (float*)(smem + B2S_OFF);

    // cp.async helpers: 512 x 16B per weight chunk, 2 per thread
    const int r0c = tid >> 3, s0c = tid & 7;            // first element
    const int r1c = (tid + 256) >> 3, s1c = tid & 7;    // second element

    // ---- pre-issue: G0 = [W1(0), W2(0)] ; G1 = [W1(1)] ----
    cp16(sb + W1_OFF + r0c * PB + s0c * 16, g_w1h + r0c * 64 + s0c * 8);
    cp16(sb + W1_OFF + r1c * PB + s1c * 16, g_w1h + r1c * 64 + s1c * 8);
    cp16(sb + W2_OFF + r0c * PB + s0c * 16, g_w2h + r0c * 256 + s0c * 8);
    cp16(sb + W2_OFF + r1c * PB + s1c * 16, g_w2h + r1c * 256 + s1c * 8);
    cp_commit();
    cp16(sb + W1_OFF + 9216 + r0c * PB + s0c * 16, g_w1h + (64 + r0c) * 64 + s0c * 8);
    cp16(sb + W1_OFF + 9216 + r1c * PB + s1c * 16, g_w1h + (64 + r1c) * 64 + s1c * 8);
    cp_commit();

    // ---- stage x -> fp16 [pix][c] ----
    for (int i = tid; i < 64 * 128; i += THREADS) {
        const int c = i >> 7, pix = i & 127;
        const int r = pix >> 5, col = pix & 31;
        const float v = x[(((size_t)b * C_IN + c) * H_SZ + (h0 + r)) * W_SZ + (w0 + col)];
        *(__half*)(smem + X_OFF + pix * PB + c * 2) = __float2half_rn(v);
    }
    if (tid < HID)  b1_s[tid] = b1[tid];
    if (tid < C_IN) b2_s[tid] = b2[tid];

    // ---- warp geometry ----
    const int pr  = wid & 3;              // pixel group (32 pix)
    const int wcg = wid >> 2;             // n group
    const int aRow = (lane & 7) + ((lane >> 3) & 1) * 8;
    const int aKof = (lane >> 4) * 8;
    const int bRow = (lane & 7) + (lane >> 4) * 8;
    const int bKof = ((lane >> 3) & 1) * 8;
    const int dRow = lane >> 2;
    const int dCol = (lane & 3) * 2;

    const uint32_t aXbase = sb + X_OFF + (uint32_t)((pr * 32 + aRow) * PB + aKof * 2);
    const uint32_t aHbase = sb + H_OFF + (uint32_t)((pr * 32 + aRow) * PB + aKof * 2);

    // persistent GEMM2 accumulators: 32 pix x 32 c per warp
    float acc2[2][4][4];
    #pragma unroll
    for (int mt = 0; mt < 2; ++mt)
        #pragma unroll
        for (int nt = 0; nt < 4; ++nt)
            #pragma unroll
            for (int j = 0; j < 4; ++j) acc2[mt][nt][j] = 0.f;

    // ---- 4 hid chunks of 64 ----
    #pragma unroll 1
    for (int nc = 0; nc < NCHUNK; ++nc) {
        const uint32_t w1buf = sb + W1_OFF + (nc & 1) * 9216;
        const uint32_t w2buf = sb + W2_OFF + (nc & 1) * 9216;

        // BARRIER A: W1(nc), W2(nc) complete; GEMM2(nc-1) retired
        if (nc < NCHUNK - 1) cp_wait<1>(); else cp_wait<0>();
        __syncthreads();

        // issue W2(nc+1) into the other buffer
        if (nc + 1 < NCHUNK) {
            const uint32_t dst = sb + W2_OFF + ((nc + 1) & 1) * 9216;
            cp16(dst + r0c * PB + s0c * 16, g_w2h + r0c * 256 + (nc + 1) * 64 + s0c * 8);
            cp16(dst + r1c * PB + s1c * 16, g_w2h + r1c * 256 + (nc + 1) * 64 + s1c * 8);
            cp_commit();
        }

        // ===== GEMM1 in two 32-hid sub-passes, each + GELU -> H =====
        #pragma unroll
        for (int sh = 0; sh < 2; ++sh) {
            float acc1[2][2][4];
            #pragma unroll
            for (int mt = 0; mt < 2; ++mt)
                #pragma unroll
                for (int nt = 0; nt < 2; ++nt)
                    #pragma unroll
                    for (int j = 0; j < 4; ++j) acc1[mt][nt][j] = 0.f;

            const uint32_t bW1 = w1buf +
                (uint32_t)((sh * 32 + wcg * 16 + bRow) * PB + bKof * 2);

            #pragma unroll
            for (int ks = 0; ks < 4; ++ks) {
                uint32_t ax[8], bh[4];
                LDSM4(ax[0], ax[1], ax[2], ax[3], aXbase + ks * 32);
                LDSM4(ax[4], ax[5], ax[6], ax[7], aXbase + 16 * PB + ks * 32);
                LDSM4(bh[0], bh[1], bh[2], bh[3], bW1 + ks * 32);
                #pragma unroll
                for (int mt = 0; mt < 2; ++mt)
                    #pragma unroll
                    for (int nt = 0; nt < 2; ++nt)
                        mma16816(acc1[mt][nt], ax + mt * 4, bh + nt * 2);
            }

            // bias + exact GELU -> fp16 -> H (cols sh*32 + wcg*16 + ...)
            #pragma unroll
            for (int mt = 0; mt < 2; ++mt)
                #pragma unroll
                for (int nt = 0; nt < 2; ++nt) {
                    const int nl = sh * 32 + wcg * 16 + nt * 8 + dCol;   // 0..63
                    const float bb0 = b1_s[nc * NH + nl];
                    const float bb1 = b1_s[nc * NH + nl + 1];
                    const int rr = pr * 32 + mt * 16 + dRow;
                    #pragma unroll
                    for (int hh = 0; hh < 2; ++hh) {
                        const float g0 = gelu_exact(acc1[mt][nt][hh * 2 + 0] + bb0);
                        const float g1 = gelu_exact(acc1[mt][nt][hh * 2 + 1] + bb1);
                        *(uint32_t*)(smem + H_OFF + (rr + hh * 8) * PB + nl * 2) =
                            ph2(__float2half_rn(g0), __float2half_rn(g1));
                    }
                }
        }

        // BARRIER B: H visible; W1(nc) reads retired
        __syncthreads();

        // issue W1(nc+2) into buf[nc&1]
        if (nc + 2 < NCHUNK) {
            const uint32_t dst = w1buf;
            cp16(dst + r0c * PB + s0c * 16, g_w1h + ((nc + 2) * 64 + r0c) * 64 + s0c * 8);
            cp16(dst + r1c * PB + s1c * 16, g_w1h + ((nc + 2) * 64 + r1c) * 64 + s1c * 8);
            cp_commit();
        }

        // ===== GEMM2: [128 pix x 64 c] += H * W2c^T, K = 64 =====
        const uint32_t bW2 = w2buf + (uint32_t)((wcg * 32 + bRow) * PB + bKof * 2);
        #pragma unroll
        for (int ks = 0; ks < 4; ++ks) {
            uint32_t ah[8], bh[8];
            LDSM4(ah[0], ah[1], ah[2], ah[3], aHbase + ks * 32);
            LDSM4(ah[4], ah[5], ah[6], ah[7], aHbase + 16 * PB + ks * 32);
            LDSM4(bh[0], bh[1], bh[2], bh[3], bW2 + ks * 32);
            LDSM4(bh[4], bh[5], bh[6], bh[7], bW2 + 16 * PB + ks * 32);
            #pragma unroll
            for (int mt = 0; mt < 2; ++mt)
                #pragma unroll
                for (int nt = 0; nt < 4; ++nt)
                    mma16816(acc2[mt][nt], ah + mt * 4, bh + nt * 2);
        }
    }

    __syncthreads();                                   // all X/H/W reads done

    // ---- y (+bias) -> y_s overlay ----
    float* y_s = (float*)(smem + YS_OFF);
    #pragma unroll
    for (int mt = 0; mt < 2; ++mt)
        #pragma unroll
        for (int nt = 0; nt < 4; ++nt) {
            const int c0 = wcg * 32 + nt * 8 + dCol;
            const int rr = pr * 32 + mt * 16 + dRow;
            #pragma unroll
            for (int hh = 0; hh < 2; ++hh) {
                y_s[(c0)     * X_PITCH + rr + hh * 8] = acc2[mt][nt][hh * 2 + 0] + b2_s[c0];
                y_s[(c0 + 1) * X_PITCH + rr + hh * 8] = acc2[mt][nt][hh * 2 + 1] + b2_s[c0 + 1];
            }
        }
    __syncthreads();

    // ---- Fourier mix: 2 windows per thread; M from global (L1-resident) ----
    const int c   = tid >> 2;          // 0..63
    const int wcb = (tid & 3) * 2;
    const float4* mrow = (const float4*)(g_M + c * 256);

    #pragma unroll
    for (int jw = 0; jw < 2; ++jw) {
        const int wc = wcb + jw;
        float pin[16];
        #pragma unroll
        for (int r4 = 0; r4 < 4; ++r4) {
            const float4 v = *(const float4*)&y_s[c * X_PITCH + r4 * 32 + wc * 4];
            pin[r4 * 4 + 0] = v.x; pin[r4 * 4 + 1] = v.y;
            pin[r4 * 4 + 2] = v.z; pin[r4 * 4 + 3] = v.w;
        }
        float po[16];
        #pragma unroll
        for (int o = 0; o < 16; ++o) {
            const float4 m0 = __ldg(mrow + o * 4 + 0);
            const float4 m1 = __ldg(mrow + o * 4 + 1);
            const float4 m2 = __ldg(mrow + o * 4 + 2);
            const float4 m3 = __ldg(mrow + o * 4 + 3);
            float s = m0.x * pin[0] + m0.y * pin[1] + m0.z * pin[2] + m0.w * pin[3];
            s += m1.x * pin[4]  + m1.y * pin[5]  + m1.z * pin[6]  + m1.w * pin[7];
            s += m2.x * pin[8]  + m2.y * pin[9]  + m2.z * pin[10] + m2.w * pin[11];
            s += m3.x * pin[12] + m3.y * pin[13] + m3.z * pin[14] + m3.w * pin[15];
            po[o] = s;
        }
        const size_t obase = (((size_t)b * C_IN + c) * H_SZ + h0) * W_SZ + w0 + wc * 4;
        #pragma unroll
        for (int r4 = 0; r4 < 4; ++r4) {
            *(float4*)&out[obase + (size_t)r4 * W_SZ] =
                make_float4(po[r4 * 4 + 0], po[r4 * 4 + 1], po[r4 * 4 + 2], po[r4 * 4 + 3]);
        }
    }
}

// ---------------------------------------------------------------------------
extern "C" void kernel_launch(void* const* d_in, const int* in_sizes, int n_in,
                              void* d_out, int out_size) {
    const float* x  = (const float*)d_in[0];
    const float* w1 = (const float*)d_in[1];
    const float* b1 = (const float*)d_in[2];
    const float* w2 = (const float*)d_in[3];
    const float* b2 = (const float*)d_in[4];
    const float* cw = (const float*)d_in[5];
    float* out = (float*)d_out;

    cudaFuncSetAttribute(fmffn_kernel,
                         cudaFuncAttributeMaxDynamicSharedMemorySize, SMEM_BYTES);

    build_mix_kernel<<<64, 256>>>(cw);
    build_weights_kernel<<<128, 256>>>(w1, w2);

    dim3 grid(W_SZ / 32, H_SZ / 4, B_SZ);   // (8, 64, 8)
    fmffn_kernel<<<grid, THREADS, SMEM_BYTES>>>(x, b1, b2, out);
}

// round 11
// speedup vs baseline: 1.4347x; 1.4347x over previous
#include <cuda_runtime.h>
#include <cuda_fp16.h>
#include <math.h>
#include <stdint.h>

#define B_SZ   8
#define C_IN   64
#define HID    256
#define H_SZ   256
#define W_SZ   256
#define THREADS 256
#define NH     32           // hid chunk
#define NCHUNK 8

// pitches (bytes)
#define XPB  144            // 64 c fp16 = 128B + 16 pad
#define HPB  80             // 32 hid fp16 = 64B + 16 pad
#define W1PB 144            // 64 c fp16
#define W2PB 80             // 32 hid fp16

// ---------------- smem layout (bytes) ----------------
#define X_OFF    0          // 128 x 144 = 18432
#define H_OFF    18432      // 128 x 80  = 10240
#define W1H_OFF  28672      // 32 x 144  = 4608
#define W1L_OFF  33280      // 4608
#define W2H_OFF  37888      // 64 x 80   = 5120
#define W2L_OFF  43008      // 5120
#define B1S_OFF  48128      // 256 f32
#define B2S_OFF  49152      // 64 f32
#define SMEM_BYTES 49408

// final-stage overlay (X+H+W1 regions, all dead after the loop)
#define YS_OFF  0           // 64 x 132 f32 = 33792
#define X_PITCH 132

// ---------------------------------------------------------------------------
__device__ __forceinline__ uint32_t smem_u32(const void* p) {
    uint32_t a;
    asm("{ .reg .u64 t; cvta.to.shared.u64 t, %1; cvt.u32.u64 %0, t; }" : "=r"(a) : "l"(p));
    return a;
}

#define LDSM4(r0, r1, r2, r3, addr) \
    asm volatile("ldmatrix.sync.aligned.m8n8.x4.shared.b16 {%0,%1,%2,%3}, [%4];" \
        : "=r"(r0), "=r"(r1), "=r"(r2), "=r"(r3) : "r"(addr))

__device__ __forceinline__ void mma16816(float* d, const uint32_t* a, const uint32_t* b) {
    asm volatile(
        "mma.sync.aligned.m16n8k16.row.col.f32.f16.f16.f32 "
        "{%0,%1,%2,%3}, {%4,%5,%6,%7}, {%8,%9}, {%0,%1,%2,%3};"
        : "+f"(d[0]), "+f"(d[1]), "+f"(d[2]), "+f"(d[3])
        : "r"(a[0]), "r"(a[1]), "r"(a[2]), "r"(a[3]), "r"(b[0]), "r"(b[1]));
}

__device__ __forceinline__ void cp16(uint32_t dst, const void* src) {
    asm volatile("cp.async.cg.shared.global [%0], [%1], 16;"
                 :: "r"(dst), "l"(__cvta_generic_to_global(src)) : "memory");
}
__device__ __forceinline__ void cp_commit() {
    asm volatile("cp.async.commit_group;" ::: "memory");
}
template <int N>
__device__ __forceinline__ void cp_wait() {
    asm volatile("cp.async.wait_group %0;" :: "n"(N) : "memory");
}

__device__ __forceinline__ uint32_t ph2(__half a, __half b) {
    uint32_t r;
    asm("mov.b32 %0, {%1, %2};" : "=r"(r)
        : "h"(__half_as_ushort(a)), "h"(__half_as_ushort(b)));
    return r;
}

// Fast GELU: 0.5x(1 + tanh(0.79788456x + 0.03567741x^3)) via MUFU.TANH.
// abs dev from exact gelu ~1.5e-4 rel; MUFU.TANH rel err ~2^-11 adds ~2.5e-4;
// both below the fp16-activation floor already present (4.16e-4 measured).
__device__ __forceinline__ float gelu_fast(float x) {
    const float x2 = x * x;
    const float u = x * fmaf(0.0356774081f, x2, 0.7978845608f);
    float t;
    asm("tanh.approx.f32 %0, %1;" : "=f"(t) : "f"(u));
    const float hx = 0.5f * x;
    return fmaf(hx, t, hx);
}

// ---------------------------------------------------------------------------
// Precomputed global scratch
// ---------------------------------------------------------------------------
__device__ float g_M[64 * 256];
__device__ __half g_w1h[HID * C_IN], g_w1l[HID * C_IN];
__device__ __half g_w2h[C_IN * HID], g_w2l[C_IN * HID];

__global__ void build_mix_kernel(const float* __restrict__ cw) {
    const int c   = blockIdx.x;
    const int t   = threadIdx.x;
    const int in  = t >> 4;
    const int out = t & 15;
    const int s  = in >> 2, tt = in & 3;
    const int p  = out >> 2, q  = out & 3;
    const float cs[4] = {1.f, 0.f, -1.f, 0.f};
    const float sn[4] = {0.f, 1.f, 0.f, -1.f};
    float tre[3] = {0.f, 0.f, 0.f};
    float tim[3] = {0.f, 0.f, 0.f};
    #pragma unroll
    for (int u = 0; u < 4; ++u) {
        const int e2 = (u * p) & 3;
        const float c2 = cs[e2], s2 = sn[e2];
        #pragma unroll
        for (int v = 0; v < 3; ++v) {
            const int e1 = (4 - ((u * s + v * tt) & 3)) & 3;
            const float yr = 0.25f * cs[e1];
            const float yi = 0.25f * sn[e1];
            const float wr = cw[((u * 3 + v) * 64 + c) * 2 + 0];
            const float wi = cw[((u * 3 + v) * 64 + c) * 2 + 1];
            const float zr = yr * wr - yi * wi;
            const float zi = yr * wi + yi * wr;
            tre[v] += zr * c2 - zi * s2;
            tim[v] += zr * s2 + zi * c2;
        }
    }
    const float sgn = (q & 1) ? -1.f : 1.f;
    g_M[c * 256 + out * 16 + in] =
        0.25f * (tre[0] + sgn * tre[2] + 2.f * (tre[1] * cs[q] - tim[1] * sn[q]));
}

__global__ void build_weights_kernel(const float* __restrict__ w1,
                                     const float* __restrict__ w2) {
    const int i = blockIdx.x * blockDim.x + threadIdx.x;   // 0..32767
    if (i < HID * C_IN) {
        const float v = w1[i];
        const __half hi = __float2half_rn(v);
        g_w1h[i] = hi;
        g_w1l[i] = __float2half_rn(v - __half2float(hi));
    } else {
        const int j = i - HID * C_IN;
        const float v = w2[j];
        const __half hi = __float2half_rn(v);
        g_w2h[j] = hi;
        g_w2l[j] = __float2half_rn(v - __half2float(hi));
    }
}

// ---------------------------------------------------------------------------
// Main kernel: fp16 activations + split-fp16 weights, occupancy 3
// ---------------------------------------------------------------------------
__global__ __launch_bounds__(THREADS, 3)
void fmffn_kernel(const float* __restrict__ x,
                  const float* __restrict__ b1,
                  const float* __restrict__ b2,
                  float* __restrict__ out) {
    extern __shared__ char smem[];
    const uint32_t sb = smem_u32(smem);

    const int tid  = threadIdx.x;
    const int wid  = tid >> 5;
    const int lane = tid & 31;
    const int b    = blockIdx.z;
    const int h0   = blockIdx.y * 4;
    const int w0   = blockIdx.x * 32;

    float* b1_s = (float*)(smem + B1S_OFF);
    float* b2_s = (float*)(smem + B2S_OFF);

    // per-thread cp.async coordinates
    const int w1row = tid >> 3, w1seg = tid & 7;     // 32 x 8
    const int w2row = tid >> 2, w2seg = tid & 3;     // 64 x 4

    // ---- prefetch chunk 0: W1 group, then W2 group ----
    cp16(sb + W1H_OFF + w1row * W1PB + w1seg * 16, g_w1h + w1row * 64 + w1seg * 8);
    cp16(sb + W1L_OFF + w1row * W1PB + w1seg * 16, g_w1l + w1row * 64 + w1seg * 8);
    cp_commit();
    cp16(sb + W2H_OFF + w2row * W2PB + w2seg * 16, g_w2h + w2row * 256 + w2seg * 8);
    cp16(sb + W2L_OFF + w2row * W2PB + w2seg * 16, g_w2l + w2row * 256 + w2seg * 8);
    cp_commit();

    // ---- stage x -> fp16 [pix][c] ----
    for (int i = tid; i < 64 * 128; i += THREADS) {
        const int c = i >> 7, pix = i & 127;
        const int r = pix >> 5, col = pix & 31;
        const float v = x[(((size_t)b * C_IN + c) * H_SZ + (h0 + r)) * W_SZ + (w0 + col)];
        *(__half*)(smem + X_OFF + pix * XPB + c * 2) = __float2half_rn(v);
    }
    if (tid < HID)  b1_s[tid] = b1[tid];
    if (tid < C_IN) b2_s[tid] = b2[tid];

    // ---- warp geometry ----
    const int pr  = wid & 3;              // pixel group (32 pix)
    const int wcg = wid >> 2;             // n group
    const int aRow = (lane & 7) + ((lane >> 3) & 1) * 8;
    const int aKof = (lane >> 4) * 8;
    const int bRow = (lane & 7) + (lane >> 4) * 8;
    const int bKof = ((lane >> 3) & 1) * 8;
    const int dRow = lane >> 2;
    const int dCol = (lane & 3) * 2;

    const uint32_t aXbase  = sb + X_OFF   + (uint32_t)((pr * 32 + aRow) * XPB + aKof * 2);
    const uint32_t aHbase  = sb + H_OFF   + (uint32_t)((pr * 32 + aRow) * HPB + aKof * 2);
    const uint32_t bW1base = sb + W1H_OFF + (uint32_t)((wcg * 16 + bRow) * W1PB + bKof * 2);
    const uint32_t bW2base = sb + W2H_OFF + (uint32_t)((wcg * 32 + bRow) * W2PB + bKof * 2);
#define W1LD (W1L_OFF - W1H_OFF)
#define W2LD (W2L_OFF - W2H_OFF)

    // persistent GEMM2 accumulators: 32 pix x 32 c per warp
    float acc2[2][4][4];
    #pragma unroll
    for (int mt = 0; mt < 2; ++mt)
        #pragma unroll
        for (int nt = 0; nt < 4; ++nt)
            #pragma unroll
            for (int j = 0; j < 4; ++j) acc2[mt][nt][j] = 0.f;

    // ---- 8 hid chunks of 32 ----
    #pragma unroll 1
    for (int nc = 0; nc < NCHUNK; ++nc) {
        cp_wait<0>();
        __syncthreads();                               // B1

        if (nc >= 1) {                                 // W2(nc): buffer freed by B1
            cp16(sb + W2H_OFF + w2row * W2PB + w2seg * 16,
                 g_w2h + w2row * 256 + nc * NH + w2seg * 8);
            cp16(sb + W2L_OFF + w2row * W2PB + w2seg * 16,
                 g_w2l + w2row * 256 + nc * NH + w2seg * 8);
            cp_commit();
        }

        // ===== GEMM1: [128 pix x 32 hid], K = 64, warp tile 32x16 =====
        float acc1[2][2][4];
        #pragma unroll
        for (int mt = 0; mt < 2; ++mt)
            #pragma unroll
            for (int nt = 0; nt < 2; ++nt)
                #pragma unroll
                for (int j = 0; j < 4; ++j) acc1[mt][nt][j] = 0.f;

        #pragma unroll
        for (int ks = 0; ks < 4; ++ks) {
            uint32_t ax[8], bh[4], bl[4];
            LDSM4(ax[0], ax[1], ax[2], ax[3], aXbase + ks * 32);
            LDSM4(ax[4], ax[5], ax[6], ax[7], aXbase + 16 * XPB + ks * 32);
            LDSM4(bh[0], bh[1], bh[2], bh[3], bW1base + ks * 32);
            LDSM4(bl[0], bl[1], bl[2], bl[3], bW1base + W1LD + ks * 32);
            #pragma unroll
            for (int mt = 0; mt < 2; ++mt)
                #pragma unroll
                for (int nt = 0; nt < 2; ++nt) {
                    mma16816(acc1[mt][nt], ax + mt * 4, bh + nt * 2);
                    mma16816(acc1[mt][nt], ax + mt * 4, bl + nt * 2);
                }
        }

        __syncthreads();                               // B2: W1c reads done

        if (nc < NCHUNK - 1) {                         // W1(nc+1)
            cp16(sb + W1H_OFF + w1row * W1PB + w1seg * 16,
                 g_w1h + (nc + 1) * NH * 64 + w1row * 64 + w1seg * 8);
            cp16(sb + W1L_OFF + w1row * W1PB + w1seg * 16,
                 g_w1l + (nc + 1) * NH * 64 + w1row * 64 + w1seg * 8);
            cp_commit();
        }

        // ---- bias + fast GELU -> fp16 -> H ----
        #pragma unroll
        for (int mt = 0; mt < 2; ++mt)
            #pragma unroll
            for (int nt = 0; nt < 2; ++nt) {
                const int nl = wcg * 16 + nt * 8 + dCol;           // 0..31
                const float bb0 = b1_s[nc * NH + nl];
                const float bb1 = b1_s[nc * NH + nl + 1];
                const int r0 = pr * 32 + mt * 16 + dRow;
                #pragma unroll
                for (int hh = 0; hh < 2; ++hh) {
                    const float g0 = gelu_fast(acc1[mt][nt][hh * 2 + 0] + bb0);
                    const float g1 = gelu_fast(acc1[mt][nt][hh * 2 + 1] + bb1);
                    *(uint32_t*)(smem + H_OFF + (r0 + hh * 8) * HPB + nl * 2) =
                        ph2(__float2half_rn(g0), __float2half_rn(g1));
                }
            }

        if (nc < NCHUNK - 1) cp_wait<1>(); else cp_wait<0>();   // W2(nc) complete
        __syncthreads();                               // B3: H + W2c visible

        // ===== GEMM2: [128 pix x 64 c] += H * W2c^T, K = 32, warp 32x32 =====
        #pragma unroll
        for (int ks = 0; ks < 2; ++ks) {
            uint32_t ah[8], bh[8], bl[8];
            LDSM4(ah[0], ah[1], ah[2], ah[3], aHbase + ks * 32);
            LDSM4(ah[4], ah[5], ah[6], ah[7], aHbase + 16 * HPB + ks * 32);
            LDSM4(bh[0], bh[1], bh[2], bh[3], bW2base + ks * 32);
            LDSM4(bh[4], bh[5], bh[6], bh[7], bW2base + 16 * W2PB + ks * 32);
            LDSM4(bl[0], bl[1], bl[2], bl[3], bW2base + W2LD + ks * 32);
            LDSM4(bl[4], bl[5], bl[6], bl[7], bW2base + W2LD + 16 * W2PB + ks * 32);
            #pragma unroll
            for (int mt = 0; mt < 2; ++mt)
                #pragma unroll
                for (int nt = 0; nt < 4; ++nt) {
                    mma16816(acc2[mt][nt], ah + mt * 4, bh + nt * 2);
                    mma16816(acc2[mt][nt], ah + mt * 4, bl + nt * 2);
                }
        }
    }

    __syncthreads();                                   // B4: all reads of X/H/W done

    // ---- y (+bias) -> y_s overlay ----
    float* y_s = (float*)(smem + YS_OFF);
    #pragma unroll
    for (int mt = 0; mt < 2; ++mt)
        #pragma unroll
        for (int nt = 0; nt < 4; ++nt) {
            const int c0 = wcg * 32 + nt * 8 + dCol;
            const int r0 = pr * 32 + mt * 16 + dRow;
            #pragma unroll
            for (int hh = 0; hh < 2; ++hh) {
                y_s[(c0)     * X_PITCH + r0 + hh * 8] = acc2[mt][nt][hh * 2 + 0] + b2_s[c0];
                y_s[(c0 + 1) * X_PITCH + r0 + hh * 8] = acc2[mt][nt][hh * 2 + 1] + b2_s[c0 + 1];
            }
        }
    __syncthreads();                                   // B5

    // ---- Fourier mix: 2 windows per thread; M from global (L1-resident) ----
    const int c   = tid >> 2;          // 0..63
    const int wcb = (tid & 3) * 2;
    const float4* mrow = (const float4*)(g_M + c * 256);

    #pragma unroll
    for (int jw = 0; jw < 2; ++jw) {
        const int wc = wcb + jw;
        float pin[16];
        #pragma unroll
        for (int r4 = 0; r4 < 4; ++r4) {
            const float4 v = *(const float4*)&y_s[c * X_PITCH + r4 * 32 + wc * 4];
            pin[r4 * 4 + 0] = v.x; pin[r4 * 4 + 1] = v.y;
            pin[r4 * 4 + 2] = v.z; pin[r4 * 4 + 3] = v.w;
        }
        float po[16];
        #pragma unroll
        for (int o = 0; o < 16; ++o) {
            const float4 m0 = __ldg(mrow + o * 4 + 0);
            const float4 m1 = __ldg(mrow + o * 4 + 1);
            const float4 m2 = __ldg(mrow + o * 4 + 2);
            const float4 m3 = __ldg(mrow + o * 4 + 3);
            float s = m0.x * pin[0] + m0.y * pin[1] + m0.z * pin[2] + m0.w * pin[3];
            s += m1.x * pin[4]  + m1.y * pin[5]  + m1.z * pin[6]  + m1.w * pin[7];
            s += m2.x * pin[8]  + m2.y * pin[9]  + m2.z * pin[10] + m2.w * pin[11];
            s += m3.x * pin[12] + m3.y * pin[13] + m3.z * pin[14] + m3.w * pin[15];
            po[o] = s;
        }
        const size_t obase = (((size_t)b * C_IN + c) * H_SZ + h0) * W_SZ + w0 + wc * 4;
        #pragma unroll
        for (int r4 = 0; r4 < 4; ++r4) {
            *(float4*)&out[obase + (size_t)r4 * W_SZ] =
                make_float4(po[r4 * 4 + 0], po[r4 * 4 + 1], po[r4 * 4 + 2], po[r4 * 4 + 3]);
        }
    }
}

// ---------------------------------------------------------------------------
extern "C" void kernel_launch(void* const* d_in, const int* in_sizes, int n_in,
                              void* d_out, int out_size) {
    const float* x  = (const float*)d_in[0];
    const float* w1 = (const float*)d_in[1];
    const float* b1 = (const float*)d_in[2];
    const float* w2 = (const float*)d_in[3];
    const float* b2 = (const float*)d_in[4];
    const float* cw = (const float*)d_in[5];
    float* out = (float*)d_out;

    cudaFuncSetAttribute(fmffn_kernel,
                         cudaFuncAttributeMaxDynamicSharedMemorySize, SMEM_BYTES);

    build_mix_kernel<<<64, 256>>>(cw);
    build_weights_kernel<<<128, 256>>>(w1, w2);

    dim3 grid(W_SZ / 32, H_SZ / 4, B_SZ);   // (8, 64, 8)
    fmffn_kernel<<<grid, THREADS, SMEM_BYTES>>>(x, b1, b2, out);
}

// round 13
// speedup vs baseline: 1.6076x; 1.1205x over previous
#include <cuda_runtime.h>
#include <cuda_fp16.h>
#include <math.h>
#include <stdint.h>

#define B_SZ   8
#define C_IN   64
#define HID    256
#define H_SZ   256
#define W_SZ   256
#define THREADS 256
#define NH     32           // hid chunk
#define NCHUNK 8

// pitches (bytes)
#define XPB  144            // 64 c fp16 = 128B + 16 pad
#define HPB  80             // 32 hid fp16 = 64B + 16 pad
#define W1PB 144            // 64 c fp16
#define W2PB 80             // 32 hid fp16

// ---------------- smem layout (bytes) ----------------
#define X_OFF    0          // 128 x 144 = 18432
#define H_OFF    18432      // 128 x 80  = 10240
#define W1H_OFF  28672      // 32 x 144  = 4608
#define W2H_OFF  37888      // 64 x 80   = 5120
#define B1S_OFF  48128      // 256 f32
#define B2S_OFF  49152      // 64 f32
#define SMEM_BYTES 49408

// final-stage overlay (X+H+W1 regions, all dead after the loop)
#define YS_OFF  0           // 64 x 132 f32 = 33792
#define X_PITCH 132

// ---------------------------------------------------------------------------
__device__ __forceinline__ uint32_t smem_u32(const void* p) {
    uint32_t a;
    asm("{ .reg .u64 t; cvta.to.shared.u64 t, %1; cvt.u32.u64 %0, t; }" : "=r"(a) : "l"(p));
    return a;
}

#define LDSM4(r0, r1, r2, r3, addr) \
    asm volatile("ldmatrix.sync.aligned.m8n8.x4.shared.b16 {%0,%1,%2,%3}, [%4];" \
        : "=r"(r0), "=r"(r1), "=r"(r2), "=r"(r3) : "r"(addr))

__device__ __forceinline__ void mma16816(float* d, const uint32_t* a, const uint32_t* b) {
    asm volatile(
        "mma.sync.aligned.m16n8k16.row.col.f32.f16.f16.f32 "
        "{%0,%1,%2,%3}, {%4,%5,%6,%7}, {%8,%9}, {%0,%1,%2,%3};"
        : "+f"(d[0]), "+f"(d[1]), "+f"(d[2]), "+f"(d[3])
        : "r"(a[0]), "r"(a[1]), "r"(a[2]), "r"(a[3]), "r"(b[0]), "r"(b[1]));
}

__device__ __forceinline__ void cp16(uint32_t dst, const void* src) {
    asm volatile("cp.async.cg.shared.global [%0], [%1], 16;"
                 :: "r"(dst), "l"(__cvta_generic_to_global(src)) : "memory");
}
__device__ __forceinline__ void cp_commit() {
    asm volatile("cp.async.commit_group;" ::: "memory");
}
template <int N>
__device__ __forceinline__ void cp_wait() {
    asm volatile("cp.async.wait_group %0;" :: "n"(N) : "memory");
}

__device__ __forceinline__ uint32_t ph2(__half a, __half b) {
    uint32_t r;
    asm("mov.b32 %0, {%1, %2};" : "=r"(r)
        : "h"(__half_as_ushort(a)), "h"(__half_as_ushort(b)));
    return r;
}

// Fast GELU via MUFU.TANH (validated r11: adds ~1.5e-4, under fp16 floor)
__device__ __forceinline__ float gelu_fast(float x) {
    const float x2 = x * x;
    const float u = x * fmaf(0.0356774081f, x2, 0.7978845608f);
    float t;
    asm("tanh.approx.f32 %0, %1;" : "=f"(t) : "f"(u));
    const float hx = 0.5f * x;
    return fmaf(hx, t, hx);
}

// ---------------------------------------------------------------------------
// Precomputed global scratch
// ---------------------------------------------------------------------------
__device__ float g_M[64 * 256];
__device__ __half g_w1h[HID * C_IN];
__device__ __half g_w2h[C_IN * HID];

__global__ void build_mix_kernel(const float* __restrict__ cw) {
    const int c   = blockIdx.x;
    const int t   = threadIdx.x;
    const int in  = t >> 4;
    const int out = t & 15;
    const int s  = in >> 2, tt = in & 3;
    const int p  = out >> 2, q  = out & 3;
    const float cs[4] = {1.f, 0.f, -1.f, 0.f};
    const float sn[4] = {0.f, 1.f, 0.f, -1.f};
    float tre[3] = {0.f, 0.f, 0.f};
    float tim[3] = {0.f, 0.f, 0.f};
    #pragma unroll
    for (int u = 0; u < 4; ++u) {
        const int e2 = (u * p) & 3;
        const float c2 = cs[e2], s2 = sn[e2];
        #pragma unroll
        for (int v = 0; v < 3; ++v) {
            const int e1 = (4 - ((u * s + v * tt) & 3)) & 3;
            const float yr = 0.25f * cs[e1];
            const float yi = 0.25f * sn[e1];
            const float wr = cw[((u * 3 + v) * 64 + c) * 2 + 0];
            const float wi = cw[((u * 3 + v) * 64 + c) * 2 + 1];
            const float zr = yr * wr - yi * wi;
            const float zi = yr * wi + yi * wr;
            tre[v] += zr * c2 - zi * s2;
            tim[v] += zr * s2 + zi * c2;
        }
    }
    const float sgn = (q & 1) ? -1.f : 1.f;
    g_M[c * 256 + out * 16 + in] =
        0.25f * (tre[0] + sgn * tre[2] + 2.f * (tre[1] * cs[q] - tim[1] * sn[q]));
}

__global__ void build_weights_kernel(const float* __restrict__ w1,
                                     const float* __restrict__ w2) {
    const int i = blockIdx.x * blockDim.x + threadIdx.x;   // 0..32767
    if (i < HID * C_IN) {
        g_w1h[i] = __float2half_rn(w1[i]);
    } else {
        const int j = i - HID * C_IN;
        g_w2h[j] = __float2half_rn(w2[j]);
    }
}

// ---------------------------------------------------------------------------
// Main kernel: fp16 activations + fp16 weights, occupancy 3
// ---------------------------------------------------------------------------
__global__ __launch_bounds__(THREADS, 3)
void fmffn_kernel(const float* __restrict__ x,
                  const float* __restrict__ b1,
                  const float* __restrict__ b2,
                  float* __restrict__ out) {
    extern __shared__ char smem[];
    const uint32_t sb = smem_u32(smem);

    const int tid  = threadIdx.x;
    const int wid  = tid >> 5;
    const int lane = tid & 31;
    const int b    = blockIdx.z;
    const int h0   = blockIdx.y * 4;
    const int w0   = blockIdx.x * 32;

    float* b1_s = (float*)(smem + B1S_OFF);
    float* b2_s = (float*)(smem + B2S_OFF);

    // per-thread cp.async coordinates (one 16B seg per thread per chunk)
    const int w1row = tid >> 3, w1seg = tid & 7;     // 32 x 8
    const int w2row = tid >> 2, w2seg = tid & 3;     // 64 x 4

    // ---- prefetch chunk 0: G0=[W1(0)], G1=[W2(0)] ----
    cp16(sb + W1H_OFF + w1row * W1PB + w1seg * 16, g_w1h + w1row * 64 + w1seg * 8);
    cp_commit();
    cp16(sb + W2H_OFF + w2row * W2PB + w2seg * 16, g_w2h + w2row * 256 + w2seg * 8);
    cp_commit();

    // ---- stage x -> fp16 [pix][c], float4 global loads ----
    for (int i = tid; i < 64 * 4 * 8; i += THREADS) {      // c(64) x r(4) x colgrp(8)
        const int c = i >> 5, r = (i >> 3) & 3, cg = i & 7;
        const float4 v = *(const float4*)&x[
            (((size_t)b * C_IN + c) * H_SZ + (h0 + r)) * W_SZ + w0 + cg * 4];
        char* dst = smem + X_OFF + (r * 32 + cg * 4) * XPB + c * 2;
        *(__half*)(dst)           = __float2half_rn(v.x);
        *(__half*)(dst + XPB)     = __float2half_rn(v.y);
        *(__half*)(dst + 2 * XPB) = __float2half_rn(v.z);
        *(__half*)(dst + 3 * XPB) = __float2half_rn(v.w);
    }
    if (tid < HID)  b1_s[tid] = b1[tid];
    if (tid < C_IN) b2_s[tid] = b2[tid];

    // ---- warp geometry ----
    const int pr  = wid & 3;              // pixel group (32 pix)
    const int wcg = wid >> 2;             // n group
    const int aRow = (lane & 7) + ((lane >> 3) & 1) * 8;
    const int aKof = (lane >> 4) * 8;
    const int bRow = (lane & 7) + (lane >> 4) * 8;
    const int bKof = ((lane >> 3) & 1) * 8;
    const int dRow = lane >> 2;
    const int dCol = (lane & 3) * 2;

    const uint32_t aXbase  = sb + X_OFF   + (uint32_t)((pr * 32 + aRow) * XPB + aKof * 2);
    const uint32_t aHbase  = sb + H_OFF   + (uint32_t)((pr * 32 + aRow) * HPB + aKof * 2);
    const uint32_t bW1base = sb + W1H_OFF + (uint32_t)((wcg * 16 + bRow) * W1PB + bKof * 2);
    const uint32_t bW2base = sb + W2H_OFF + (uint32_t)((wcg * 32 + bRow) * W2PB + bKof * 2);

    // persistent GEMM2 accumulators: 32 pix x 32 c per warp
    float acc2[2][4][4];
    #pragma unroll
    for (int mt = 0; mt < 2; ++mt)
        #pragma unroll
        for (int nt = 0; nt < 4; ++nt)
            #pragma unroll
            for (int j = 0; j < 4; ++j) acc2[mt][nt][j] = 0.f;

    // ---- 8 hid chunks of 32 ----
    #pragma unroll 1
    for (int nc = 0; nc < NCHUNK; ++nc) {
        cp_wait<0>();
        __syncthreads();                               // B1

        if (nc >= 1) {                                 // W2(nc): buffer freed by B1
            cp16(sb + W2H_OFF + w2row * W2PB + w2seg * 16,
                 g_w2h + w2row * 256 + nc * NH + w2seg * 8);
            cp_commit();
        }

        // ===== GEMM1: [128 pix x 32 hid], K = 64, warp tile 32x16 =====
        float acc1[2][2][4];
        #pragma unroll
        for (int mt = 0; mt < 2; ++mt)
            #pragma unroll
            for (int nt = 0; nt < 2; ++nt)
                #pragma unroll
                for (int j = 0; j < 4; ++j) acc1[mt][nt][j] = 0.f;

        #pragma unroll
        for (int ks = 0; ks < 4; ++ks) {
            uint32_t ax[8], bh[4];
            LDSM4(ax[0], ax[1], ax[2], ax[3], aXbase + ks * 32);
            LDSM4(ax[4], ax[5], ax[6], ax[7], aXbase + 16 * XPB + ks * 32);
            LDSM4(bh[0], bh[1], bh[2], bh[3], bW1base + ks * 32);
            #pragma unroll
            for (int mt = 0; mt < 2; ++mt)
                #pragma unroll
                for (int nt = 0; nt < 2; ++nt)
                    mma16816(acc1[mt][nt], ax + mt * 4, bh + nt * 2);
        }

        __syncthreads();                               // B2: W1c reads done

        if (nc < NCHUNK - 1) {                         // W1(nc+1)
            cp16(sb + W1H_OFF + w1row * W1PB + w1seg * 16,
                 g_w1h + (nc + 1) * NH * 64 + w1row * 64 + w1seg * 8);
            cp_commit();
        }

        // ---- bias + fast GELU -> fp16 -> H ----
        #pragma unroll
        for (int mt = 0; mt < 2; ++mt)
            #pragma unroll
            for (int nt = 0; nt < 2; ++nt) {
                const int nl = wcg * 16 + nt * 8 + dCol;           // 0..31
                const float bb0 = b1_s[nc * NH + nl];
                const float bb1 = b1_s[nc * NH + nl + 1];
                const int r0 = pr * 32 + mt * 16 + dRow;
                #pragma unroll
                for (int hh = 0; hh < 2; ++hh) {
                    const float g0 = gelu_fast(acc1[mt][nt][hh * 2 + 0] + bb0);
                    const float g1 = gelu_fast(acc1[mt][nt][hh * 2 + 1] + bb1);
                    *(uint32_t*)(smem + H_OFF + (r0 + hh * 8) * HPB + nl * 2) =
                        ph2(__float2half_rn(g0), __float2half_rn(g1));
                }
            }

        if (nc < NCHUNK - 1) cp_wait<1>(); else cp_wait<0>();   // W2(nc) complete
        __syncthreads();                               // B3: H + W2c visible

        // ===== GEMM2: [128 pix x 64 c] += H * W2c^T, K = 32, warp 32x32 =====
        #pragma unroll
        for (int ks = 0; ks < 2; ++ks) {
            uint32_t ah[8], bh[8];
            LDSM4(ah[0], ah[1], ah[2], ah[3], aHbase + ks * 32);
            LDSM4(ah[4], ah[5], ah[6], ah[7], aHbase + 16 * HPB + ks * 32);
            LDSM4(bh[0], bh[1], bh[2], bh[3], bW2base + ks * 32);
            LDSM4(bh[4], bh[5], bh[6], bh[7], bW2base + 16 * W2PB + ks * 32);
            #pragma unroll
            for (int mt = 0; mt < 2; ++mt)
                #pragma unroll
                for (int nt = 0; nt < 4; ++nt)
                    mma16816(acc2[mt][nt], ah + mt * 4, bh + nt * 2);
        }
    }

    __syncthreads();                                   // B4: all reads of X/H/W done

    // ---- y (+bias) -> y_s overlay ----
    float* y_s = (float*)(smem + YS_OFF);
    #pragma unroll
    for (int mt = 0; mt < 2; ++mt)
        #pragma unroll
        for (int nt = 0; nt < 4; ++nt) {
            const int c0 = wcg * 32 + nt * 8 + dCol;
            const int r0 = pr * 32 + mt * 16 + dRow;
            #pragma unroll
            for (int hh = 0; hh < 2; ++hh) {
                y_s[(c0)     * X_PITCH + r0 + hh * 8] = acc2[mt][nt][hh * 2 + 0] + b2_s[c0];
                y_s[(c0 + 1) * X_PITCH + r0 + hh * 8] = acc2[mt][nt][hh * 2 + 1] + b2_s[c0 + 1];
            }
        }
    __syncthreads();                                   // B5

    // ---- Fourier mix: 2 windows per thread, M loads hoisted across windows ----
    const int c   = tid >> 2;          // 0..63
    const int wcb = (tid & 3) * 2;
    const float4* mrow = (const float4*)(g_M + c * 256);

    float pin[32];
    #pragma unroll
    for (int jw = 0; jw < 2; ++jw) {
        const int wc = wcb + jw;
        #pragma unroll
        for (int r4 = 0; r4 < 4; ++r4) {
            const float4 v = *(const float4*)&y_s[c * X_PITCH + r4 * 32 + wc * 4];
            pin[jw * 16 + r4 * 4 + 0] = v.x; pin[jw * 16 + r4 * 4 + 1] = v.y;
            pin[jw * 16 + r4 * 4 + 2] = v.z; pin[jw * 16 + r4 * 4 + 3] = v.w;
        }
    }

    float po[32];
    #pragma unroll
    for (int o = 0; o < 16; ++o) {
        const float4 m0 = __ldg(mrow + o * 4 + 0);
        const float4 m1 = __ldg(mrow + o * 4 + 1);
        const float4 m2 = __ldg(mrow + o * 4 + 2);
        const float4 m3 = __ldg(mrow + o * 4 + 3);
        float s0 = m0.x * pin[0] + m0.y * pin[1] + m0.z * pin[2] + m0.w * pin[3];
        s0 += m1.x * pin[4]  + m1.y * pin[5]  + m1.z * pin[6]  + m1.w * pin[7];
        s0 += m2.x * pin[8]  + m2.y * pin[9]  + m2.z * pin[10] + m2.w * pin[11];
        s0 += m3.x * pin[12] + m3.y * pin[13] + m3.z * pin[14] + m3.w * pin[15];
        float s1 = m0.x * pin[16] + m0.y * pin[17] + m0.z * pin[18] + m0.w * pin[19];
        s1 += m1.x * pin[20] + m1.y * pin[21] + m1.z * pin[22] + m1.w * pin[23];
        s1 += m2.x * pin[24] + m2.y * pin[25] + m2.z * pin[26] + m2.w * pin[27];
        s1 += m3.x * pin[28] + m3.y * pin[29] + m3.z * pin[30] + m3.w * pin[31];
        po[o] = s0;
        po[16 + o] = s1;
    }

    #pragma unroll
    for (int jw = 0; jw < 2; ++jw) {
        const int wc = wcb + jw;
        const size_t obase = (((size_t)b * C_IN + c) * H_SZ + h0) * W_SZ + w0 + wc * 4;
        #pragma unroll
        for (int r4 = 0; r4 < 4; ++r4) {
            *(float4*)&out[obase + (size_t)r4 * W_SZ] =
                make_float4(po[jw * 16 + r4 * 4 + 0], po[jw * 16 + r4 * 4 + 1],
                            po[jw * 16 + r4 * 4 + 2], po[jw * 16 + r4 * 4 + 3]);
        }
    }
}

// ---------------------------------------------------------------------------
extern "C" void kernel_launch(void* const* d_in, const int* in_sizes, int n_in,
                              void* d_out, int out_size) {
    const float* x  = (const float*)d_in[0];
    const float* w1 = (const float*)d_in[1];
    const float* b1 = (const float*)d_in[2];
    const float* w2 = (const float*)d_in[3];
    const float* b2 = (const float*)d_in[4];
    const float* cw = (const float*)d_in[5];
    float* out = (float*)d_out;

    cudaFuncSetAttribute(fmffn_kernel,
                         cudaFuncAttributeMaxDynamicSharedMemorySize, SMEM_BYTES);

    build_mix_kernel<<<64, 256>>>(cw);
    build_weights_kernel<<<128, 256>>>(w1, w2);

    dim3 grid(W_SZ / 32, H_SZ / 4, B_SZ);   // (8, 64, 8)
    fmffn_kernel<<<grid, THREADS, SMEM_BYTES>>>(x, b1, b2, out);
}

// round 14
// speedup vs baseline: 1.8464x; 1.1485x over previous
#include <cuda_runtime.h>
#include <cuda_fp16.h>
#include <math.h>
#include <stdint.h>

#define B_SZ   8
#define C_IN   64
#define HID    256
#define H_SZ   256
#define W_SZ   256
#define THREADS 256
#define NH     32           // hid chunk
#define NCHUNK 8

// pitches (bytes)
#define XPB  144            // 64 c fp16 = 128B + 16 pad
#define HPB  80             // 32 hid fp16 = 64B + 16 pad
#define W1PB 144
#define W2PB 80

// ---------------- smem layout (bytes) ----------------
#define X_OFF    0          // 128 x 144 = 18432
#define H_OFF    18432      // 128 x 80  = 10240
#define W1_OFF   28672      // 2 bufs x 4608
#define W2_OFF   37888      // 2 bufs x 5120
#define B1S_OFF  48128      // 256 f32
#define B2S_OFF  49152      // 64 f32
#define SMEM_BYTES 49408

// final-phase overlays (X/H/W1/W2/B1 all dead after the loop)
#define YH_OFF  0           // yh[c][win][k] fp16: 64*8*16*2 = 16384
#define MH_OFF  16384       // Mh[c][m][k] fp16: 64*16*16*2 = 32768 (ends 49152)

// ---------------------------------------------------------------------------
__device__ __forceinline__ uint32_t smem_u32(const void* p) {
    uint32_t a;
    asm("{ .reg .u64 t; cvta.to.shared.u64 t, %1; cvt.u32.u64 %0, t; }" : "=r"(a) : "l"(p));
    return a;
}

#define LDSM4(r0, r1, r2, r3, addr) \
    asm volatile("ldmatrix.sync.aligned.m8n8.x4.shared.b16 {%0,%1,%2,%3}, [%4];" \
        : "=r"(r0), "=r"(r1), "=r"(r2), "=r"(r3) : "r"(addr))

#define LDSM2(r0, r1, addr) \
    asm volatile("ldmatrix.sync.aligned.m8n8.x2.shared.b16 {%0,%1}, [%2];" \
        : "=r"(r0), "=r"(r1) : "r"(addr))

__device__ __forceinline__ void mma16816(float* d, const uint32_t* a, const uint32_t* b) {
    asm volatile(
        "mma.sync.aligned.m16n8k16.row.col.f32.f16.f16.f32 "
        "{%0,%1,%2,%3}, {%4,%5,%6,%7}, {%8,%9}, {%0,%1,%2,%3};"
        : "+f"(d[0]), "+f"(d[1]), "+f"(d[2]), "+f"(d[3])
        : "r"(a[0]), "r"(a[1]), "r"(a[2]), "r"(a[3]), "r"(b[0]), "r"(b[1]));
}

__device__ __forceinline__ void cp16(uint32_t dst, const void* src) {
    asm volatile("cp.async.cg.shared.global [%0], [%1], 16;"
                 :: "r"(dst), "l"(__cvta_generic_to_global(src)) : "memory");
}
__device__ __forceinline__ void cp_commit() {
    asm volatile("cp.async.commit_group;" ::: "memory");
}
template <int N>
__device__ __forceinline__ void cp_wait() {
    asm volatile("cp.async.wait_group %0;" :: "n"(N) : "memory");
}

__device__ __forceinline__ uint32_t ph2(__half a, __half b) {
    uint32_t r;
    asm("mov.b32 %0, {%1, %2};" : "=r"(r)
        : "h"(__half_as_ushort(a)), "h"(__half_as_ushort(b)));
    return r;
}

// Fast GELU via MUFU.TANH (validated r11)
__device__ __forceinline__ float gelu_fast(float x) {
    const float x2 = x * x;
    const float u = x * fmaf(0.0356774081f, x2, 0.7978845608f);
    float t;
    asm("tanh.approx.f32 %0, %1;" : "=f"(t) : "f"(u));
    const float hx = 0.5f * x;
    return fmaf(hx, t, hx);
}

// ---------------------------------------------------------------------------
// Precomputed global scratch
// ---------------------------------------------------------------------------
__device__ __half g_Mh[64 * 256];        // [c][out m(16)][in k(16)]
__device__ __half g_w1h[HID * C_IN];
__device__ __half g_w2h[C_IN * HID];

__global__ void build_mix_kernel(const float* __restrict__ cw) {
    const int c   = blockIdx.x;
    const int t   = threadIdx.x;
    const int in  = t >> 4;
    const int out = t & 15;
    const int s  = in >> 2, tt = in & 3;
    const int p  = out >> 2, q  = out & 3;
    const float cs[4] = {1.f, 0.f, -1.f, 0.f};
    const float sn[4] = {0.f, 1.f, 0.f, -1.f};
    float tre[3] = {0.f, 0.f, 0.f};
    float tim[3] = {0.f, 0.f, 0.f};
    #pragma unroll
    for (int u = 0; u < 4; ++u) {
        const int e2 = (u * p) & 3;
        const float c2 = cs[e2], s2 = sn[e2];
        #pragma unroll
        for (int v = 0; v < 3; ++v) {
            const int e1 = (4 - ((u * s + v * tt) & 3)) & 3;
            const float yr = 0.25f * cs[e1];
            const float yi = 0.25f * sn[e1];
            const float wr = cw[((u * 3 + v) * 64 + c) * 2 + 0];
            const float wi = cw[((u * 3 + v) * 64 + c) * 2 + 1];
            const float zr = yr * wr - yi * wi;
            const float zi = yr * wi + yi * wr;
            tre[v] += zr * c2 - zi * s2;
            tim[v] += zr * s2 + zi * c2;
        }
    }
    const float sgn = (q & 1) ? -1.f : 1.f;
    const float val =
        0.25f * (tre[0] + sgn * tre[2] + 2.f * (tre[1] * cs[q] - tim[1] * sn[q]));
    g_Mh[c * 256 + out * 16 + in] = __float2half_rn(val);
}

__global__ void build_weights_kernel(const float* __restrict__ w1,
                                     const float* __restrict__ w2) {
    const int i = blockIdx.x * blockDim.x + threadIdx.x;   // 0..32767
    if (i < HID * C_IN) {
        g_w1h[i] = __float2half_rn(w1[i]);
    } else {
        const int j = i - HID * C_IN;
        g_w2h[j] = __float2half_rn(w2[j]);
    }
}

// ---------------------------------------------------------------------------
// Main kernel
// ---------------------------------------------------------------------------
__global__ __launch_bounds__(THREADS, 3)
void fmffn_kernel(const float* __restrict__ x,
                  const float* __restrict__ b1,
                  const float* __restrict__ b2,
                  float* __restrict__ out) {
    extern __shared__ char smem[];
    const uint32_t sb = smem_u32(smem);

    const int tid  = threadIdx.x;
    const int wid  = tid >> 5;
    const int lane = tid & 31;
    const int b    = blockIdx.z;
    const int h0   = blockIdx.y * 4;
    const int w0   = blockIdx.x * 32;

    float* b1_s = (float*)(smem + B1S_OFF);
    float* b2_s = (float*)(smem + B2S_OFF);

    // per-thread cp.async coordinates
    const int w1row = tid >> 3, w1seg = tid & 7;     // 32 x 8
    const int w2row = tid >> 2, w2seg = tid & 3;     // 64 x 4

    // ---- pre-issue 4 groups: W1(0), W2(0), W1(1), W2(1) ----
    cp16(sb + W1_OFF + w1row * W1PB + w1seg * 16, g_w1h + w1row * 64 + w1seg * 8);
    cp_commit();
    cp16(sb + W2_OFF + w2row * W2PB + w2seg * 16, g_w2h + w2row * 256 + w2seg * 8);
    cp_commit();
    cp16(sb + W1_OFF + 4608 + w1row * W1PB + w1seg * 16,
         g_w1h + NH * 64 + w1row * 64 + w1seg * 8);
    cp_commit();
    cp16(sb + W2_OFF + 5120 + w2row * W2PB + w2seg * 16,
         g_w2h + w2row * 256 + NH + w2seg * 8);
    cp_commit();

    // ---- stage x -> fp16 [pix][c], float4 global loads ----
    for (int i = tid; i < 64 * 4 * 8; i += THREADS) {      // c(64) x r(4) x colgrp(8)
        const int c = i >> 5, r = (i >> 3) & 3, cg = i & 7;
        const float4 v = *(const float4*)&x[
            (((size_t)b * C_IN + c) * H_SZ + (h0 + r)) * W_SZ + w0 + cg * 4];
        char* dst = smem + X_OFF + (r * 32 + cg * 4) * XPB + c * 2;
        *(__half*)(dst)           = __float2half_rn(v.x);
        *(__half*)(dst + XPB)     = __float2half_rn(v.y);
        *(__half*)(dst + 2 * XPB) = __float2half_rn(v.z);
        *(__half*)(dst + 3 * XPB) = __float2half_rn(v.w);
    }
    if (tid < HID)  b1_s[tid] = b1[tid];
    if (tid < C_IN) b2_s[tid] = b2[tid];

    // ---- warp geometry ----
    const int pr  = wid & 3;              // pixel row group (32 cols of one h-row set)
    const int wcg = wid >> 2;             // n group
    const int aRow = (lane & 7) + ((lane >> 3) & 1) * 8;
    const int aKof = (lane >> 4) * 8;
    const int bRow = (lane & 7) + (lane >> 4) * 8;
    const int bKof = ((lane >> 3) & 1) * 8;
    const int dRow = lane >> 2;
    const int dCol = (lane & 3) * 2;

    const uint32_t aXbase = sb + X_OFF + (uint32_t)((pr * 32 + aRow) * XPB + aKof * 2);
    const uint32_t aHbase = sb + H_OFF + (uint32_t)((pr * 32 + aRow) * HPB + aKof * 2);
    const uint32_t bW1off = (uint32_t)((wcg * 16 + bRow) * W1PB + bKof * 2);
    const uint32_t bW2off = (uint32_t)((wcg * 32 + bRow) * W2PB + bKof * 2);

    // persistent GEMM2 accumulators: 32 pix x 32 c per warp
    float acc2[2][4][4];
    #pragma unroll
    for (int mt = 0; mt < 2; ++mt)
        #pragma unroll
        for (int nt = 0; nt < 4; ++nt)
            #pragma unroll
            for (int j = 0; j < 4; ++j) acc2[mt][nt][j] = 0.f;

    // ---- 8 hid chunks of 32 ----
    #pragma unroll 1
    for (int nc = 0; nc < NCHUNK; ++nc) {
        const uint32_t w1buf = sb + W1_OFF + (nc & 1) * 4608;
        const uint32_t w2buf = sb + W2_OFF + (nc & 1) * 5120;

        // B1: W1(nc) + W2(nc) arrived; GEMM2(nc-1) retired
        if (nc == 0)                cp_wait<2>();
        else if (nc == NCHUNK - 1)  cp_wait<0>();
        else                        cp_wait<1>();
        __syncthreads();

        // issue W2(nc+1) (buffer parity (nc+1)&1 freed by this B1)
        if (nc >= 1 && nc + 1 < NCHUNK) {
            cp16(sb + W2_OFF + ((nc + 1) & 1) * 5120 + w2row * W2PB + w2seg * 16,
                 g_w2h + w2row * 256 + (nc + 1) * NH + w2seg * 8);
            cp_commit();
        }

        // ===== GEMM1: [128 pix x 32 hid], K = 64, warp tile 32x16 =====
        float acc1[2][2][4];
        #pragma unroll
        for (int mt = 0; mt < 2; ++mt)
            #pragma unroll
            for (int nt = 0; nt < 2; ++nt)
                #pragma unroll
                for (int j = 0; j < 4; ++j) acc1[mt][nt][j] = 0.f;

        #pragma unroll
        for (int ks = 0; ks < 4; ++ks) {
            uint32_t ax[8], bh[4];
            LDSM4(ax[0], ax[1], ax[2], ax[3], aXbase + ks * 32);
            LDSM4(ax[4], ax[5], ax[6], ax[7], aXbase + 16 * XPB + ks * 32);
            LDSM4(bh[0], bh[1], bh[2], bh[3], w1buf + bW1off + ks * 32);
            #pragma unroll
            for (int mt = 0; mt < 2; ++mt)
                #pragma unroll
                for (int nt = 0; nt < 2; ++nt)
                    mma16816(acc1[mt][nt], ax + mt * 4, bh + nt * 2);
        }

        // ---- bias + fast GELU -> fp16 -> H ----
        #pragma unroll
        for (int mt = 0; mt < 2; ++mt)
            #pragma unroll
            for (int nt = 0; nt < 2; ++nt) {
                const int nl = wcg * 16 + nt * 8 + dCol;           // 0..31
                const float bb0 = b1_s[nc * NH + nl];
                const float bb1 = b1_s[nc * NH + nl + 1];
                const int r0 = pr * 32 + mt * 16 + dRow;
                #pragma unroll
                for (int hh = 0; hh < 2; ++hh) {
                    const float g0 = gelu_fast(acc1[mt][nt][hh * 2 + 0] + bb0);
                    const float g1 = gelu_fast(acc1[mt][nt][hh * 2 + 1] + bb1);
                    *(uint32_t*)(smem + H_OFF + (r0 + hh * 8) * HPB + nl * 2) =
                        ph2(__float2half_rn(g0), __float2half_rn(g1));
                }
            }

        // B3: H visible; all GEMM1(nc) W1-buf reads retired
        __syncthreads();

        // issue W1(nc+2) into buf parity nc&1 (just retired by B3)
        if (nc + 2 < NCHUNK) {
            cp16(w1buf + w1row * W1PB + w1seg * 16,
                 g_w1h + (nc + 2) * NH * 64 + w1row * 64 + w1seg * 8);
            cp_commit();
        }

        // ===== GEMM2: [128 pix x 64 c] += H * W2c^T, K = 32, warp 32x32 =====
        #pragma unroll
        for (int ks = 0; ks < 2; ++ks) {
            uint32_t ah[8], bh[8];
            LDSM4(ah[0], ah[1], ah[2], ah[3], aHbase + ks * 32);
            LDSM4(ah[4], ah[5], ah[6], ah[7], aHbase + 16 * HPB + ks * 32);
            LDSM4(bh[0], bh[1], bh[2], bh[3], w2buf + bW2off + ks * 32);
            LDSM4(bh[4], bh[5], bh[6], bh[7], w2buf + bW2off + 16 * W2PB + ks * 32);
            #pragma unroll
            for (int mt = 0; mt < 2; ++mt)
                #pragma unroll
                for (int nt = 0; nt < 4; ++nt)
                    mma16816(acc2[mt][nt], ah + mt * 4, bh + nt * 2);
        }
    }

    __syncthreads();                                   // B4: all X/H/W reads done

    // ---- issue Mh copy into overlay (X/H/W1/W2/B1 regions dead) ----
    for (int i = tid; i < 2048; i += THREADS)
        cp16(sb + MH_OFF + i * 16, (const char*)g_Mh + i * 16);
    cp_commit();

    // ---- y (+b2) -> yh[c][win][k] fp16 overlay ----
    #pragma unroll
    for (int mt = 0; mt < 2; ++mt)
        #pragma unroll
        for (int nt = 0; nt < 4; ++nt) {
            const int c0 = wcg * 32 + nt * 8 + dCol;
            #pragma unroll
            for (int hh = 0; hh < 2; ++hh) {
                const int col = mt * 16 + hh * 8 + dRow;       // 0..31
                const int win = col >> 2;
                const int kk  = pr * 4 + (col & 3);            // in-patch index
                const uint32_t o = (uint32_t)(win * 32 + kk * 2);
                *(__half*)(smem + YH_OFF + c0 * 256 + o) =
                    __float2half_rn(acc2[mt][nt][hh * 2 + 0] + b2_s[c0]);
                *(__half*)(smem + YH_OFF + (c0 + 1) * 256 + o) =
                    __float2half_rn(acc2[mt][nt][hh * 2 + 1] + b2_s[c0 + 1]);
            }
        }
    cp_wait<0>();
    __syncthreads();                                   // B5: yh + Mh ready

    // ---- Fourier mix via mma: 8 channels per warp, 1 mma each ----
    // A = M_c [m=16][k=16] row-major; B = yh[c] [n=win(8)][k=16] k-contig
    const uint32_t aoff = sb + MH_OFF +
        (uint32_t)((((lane & 7) + ((lane >> 3) & 1) * 8) * 16 + ((lane >> 4) & 1) * 8) * 2);
    const uint32_t boff = sb + YH_OFF +
        (uint32_t)(((lane & 7) * 16 + ((lane >> 3) & 1) * 8) * 2);
    const int cb = wid * 8;

    #pragma unroll
    for (int j = 0; j < 8; ++j) {
        const int c = cb + j;
        uint32_t a[4], bb[2];
        LDSM4(a[0], a[1], a[2], a[3], aoff + c * 512);
        LDSM2(bb[0], bb[1], boff + c * 256);
        float d[4] = {0.f, 0.f, 0.f, 0.f};
        mma16816(d, a, bb);
        // lane holds m in {dRow, dRow+8}, n in {dCol, dCol+1}
        // m -> (h-row = m>>2, q = m&3); out col = w0 + n*4 + q
        const size_t base = (((size_t)(b * C_IN + c)) * H_SZ + h0 + (dRow >> 2)) * W_SZ
                          + w0 + dCol * 4 + (dRow & 3);
        out[base]           = d[0];
        out[base + 4]       = d[1];
        out[base + 2 * 256] = d[2];
        out[base + 2 * 256 + 4] = d[3];
    }
}

// ---------------------------------------------------------------------------
extern "C" void kernel_launch(void* const* d_in, const int* in_sizes, int n_in,
                              void* d_out, int out_size) {
    const float* x  = (const float*)d_in[0];
    const float* w1 = (const float*)d_in[1];
    const float* b1 = (const float*)d_in[2];
    const float* w2 = (const float*)d_in[3];
    const float* b2 = (const float*)d_in[4];
    const float* cw = (const float*)d_in[5];
    float* out = (float*)d_out;

    cudaFuncSetAttribute(fmffn_kernel,
                         cudaFuncAttributeMaxDynamicSharedMemorySize, SMEM_BYTES);

    build_mix_kernel<<<64, 256>>>(cw);
    build_weights_kernel<<<128, 256>>>(w1, w2);

    dim3 grid(W_SZ / 32, H_SZ / 4, B_SZ);   // (8, 64, 8)
    fmffn_kernel<<<grid, THREADS, SMEM_BYTES>>>(x, b1, b2, out);
}

// round 15
// speedup vs baseline: 1.9145x; 1.0369x over previous
#include <cuda_runtime.h>
#include <cuda_fp16.h>
#include <math.h>
#include <stdint.h>

#define B_SZ   8
#define C_IN   64
#define HID    256
#define H_SZ   256
#define W_SZ   256
#define THREADS 256
#define NH     32           // hid chunk
#define NCHUNK 8

// pitches (bytes)
#define XPB  144            // 64 c fp16 = 128B + 16 pad
#define HPB  80             // 32 hid fp16 = 64B + 16 pad
#define W1PB 144
#define W2PB 80

// ---------------- smem layout (bytes) ----------------
#define X_OFF    0          // 128 x 144 = 18432
#define H_OFF    18432      // 128 x 80  = 10240
#define W1_OFF   28672      // 2 bufs x 4608
#define W2_OFF   37888      // 2 bufs x 5120
#define B1S_OFF  48128      // 256 f32
#define B2S_OFF  49152      // 64 f32
#define SMEM_BYTES 49408

// final-phase overlays (X/H/W1/W2/B1 all dead after the loop)
#define YH_OFF  0           // yh[c][win][k] fp16: 64*8*16*2 = 16384
#define MH_OFF  16384       // Mh[c][m][k] fp16: 64*16*16*2 = 32768 (ends 49152)

// ---------------------------------------------------------------------------
__device__ __forceinline__ uint32_t smem_u32(const void* p) {
    uint32_t a;
    asm("{ .reg .u64 t; cvta.to.shared.u64 t, %1; cvt.u32.u64 %0, t; }" : "=r"(a) : "l"(p));
    return a;
}

#define LDSM4(r0, r1, r2, r3, addr) \
    asm volatile("ldmatrix.sync.aligned.m8n8.x4.shared.b16 {%0,%1,%2,%3}, [%4];" \
        : "=r"(r0), "=r"(r1), "=r"(r2), "=r"(r3) : "r"(addr))

#define LDSM2(r0, r1, addr) \
    asm volatile("ldmatrix.sync.aligned.m8n8.x2.shared.b16 {%0,%1}, [%2];" \
        : "=r"(r0), "=r"(r1) : "r"(addr))

__device__ __forceinline__ void mma16816(float* d, const uint32_t* a, const uint32_t* b) {
    asm volatile(
        "mma.sync.aligned.m16n8k16.row.col.f32.f16.f16.f32 "
        "{%0,%1,%2,%3}, {%4,%5,%6,%7}, {%8,%9}, {%0,%1,%2,%3};"
        : "+f"(d[0]), "+f"(d[1]), "+f"(d[2]), "+f"(d[3])
        : "r"(a[0]), "r"(a[1]), "r"(a[2]), "r"(a[3]), "r"(b[0]), "r"(b[1]));
}

__device__ __forceinline__ void cp16(uint32_t dst, const void* src) {
    asm volatile("cp.async.cg.shared.global [%0], [%1], 16;"
                 :: "r"(dst), "l"(__cvta_generic_to_global(src)) : "memory");
}
__device__ __forceinline__ void cp_commit() {
    asm volatile("cp.async.commit_group;" ::: "memory");
}
template <int N>
__device__ __forceinline__ void cp_wait() {
    asm volatile("cp.async.wait_group %0;" :: "n"(N) : "memory");
}

// Packed half2 GELU: z = cvt(a0,a1)+bias; r = 0.5z(1+tanh(z(0.798+0.0357 z^2)))
// All fp16x2 math incl. MUFU tanh.f16x2. Returns packed half2 bits.
__device__ __forceinline__ uint32_t gelu2(float a0, float a1, __half2 bias) {
    const __half2 cA = __floats2half2_rn(0.7978845608f, 0.7978845608f);
    const __half2 cB = __floats2half2_rn(0.0356774081f, 0.0356774081f);
    __half2 z  = __hadd2(__floats2half2_rn(a0, a1), bias);
    __half2 z2 = __hmul2(z, z);
    __half2 u  = __hmul2(z, __hfma2(cB, z2, cA));
    uint32_t tu;
    asm("tanh.approx.f16x2 %0, %1;" : "=r"(tu) : "r"(*(uint32_t*)&u));
    __half2 t  = *(__half2*)&tu;
    __half2 hz = __hmul2(z, __floats2half2_rn(0.5f, 0.5f));
    __half2 r  = __hfma2(hz, t, hz);
    return *(uint32_t*)&r;
}

// ---------------------------------------------------------------------------
// Precomputed global scratch
// ---------------------------------------------------------------------------
__device__ __half g_Mh[64 * 256];        // [c][out m(16)][in k(16)]
__device__ __half g_w1h[HID * C_IN];
__device__ __half g_w2h[C_IN * HID];

// Merged builder: blocks 0..63 build mix matrices; blocks 64..95 build weights
__global__ void build_all_kernel(const float* __restrict__ cw,
                                 const float* __restrict__ w1,
                                 const float* __restrict__ w2) {
    if (blockIdx.x < 64) {
        const int c   = blockIdx.x;
        const int t   = threadIdx.x;
        const int in  = t >> 4;
        const int out = t & 15;
        const int s  = in >> 2, tt = in & 3;
        const int p  = out >> 2, q  = out & 3;
        const float cs[4] = {1.f, 0.f, -1.f, 0.f};
        const float sn[4] = {0.f, 1.f, 0.f, -1.f};
        float tre[3] = {0.f, 0.f, 0.f};
        float tim[3] = {0.f, 0.f, 0.f};
        #pragma unroll
        for (int u = 0; u < 4; ++u) {
            const int e2 = (u * p) & 3;
            const float c2 = cs[e2], s2 = sn[e2];
            #pragma unroll
            for (int v = 0; v < 3; ++v) {
                const int e1 = (4 - ((u * s + v * tt) & 3)) & 3;
                const float yr = 0.25f * cs[e1];
                const float yi = 0.25f * sn[e1];
                const float wr = cw[((u * 3 + v) * 64 + c) * 2 + 0];
                const float wi = cw[((u * 3 + v) * 64 + c) * 2 + 1];
                const float zr = yr * wr - yi * wi;
                const float zi = yr * wi + yi * wr;
                tre[v] += zr * c2 - zi * s2;
                tim[v] += zr * s2 + zi * c2;
            }
        }
        const float sgn = (q & 1) ? -1.f : 1.f;
        const float val =
            0.25f * (tre[0] + sgn * tre[2] + 2.f * (tre[1] * cs[q] - tim[1] * sn[q]));
        g_Mh[c * 256 + out * 16 + in] = __float2half_rn(val);
    } else {
        const int base = (blockIdx.x - 64) * THREADS + threadIdx.x;  // 0..8191
        #pragma unroll
        for (int k = 0; k < 4; ++k) {
            const int i = base + k * 8192;                           // 0..32767
            if (i < HID * C_IN) {
                g_w1h[i] = __float2half_rn(w1[i]);
            } else {
                const int j = i - HID * C_IN;
                g_w2h[j] = __float2half_rn(w2[j]);
            }
        }
    }
}

// ---------------------------------------------------------------------------
// Main kernel
// ---------------------------------------------------------------------------
__global__ __launch_bounds__(THREADS, 3)
void fmffn_kernel(const float* __restrict__ x,
                  const float* __restrict__ b1,
                  const float* __restrict__ b2,
                  float* __restrict__ out) {
    extern __shared__ char smem[];
    const uint32_t sb = smem_u32(smem);

    const int tid  = threadIdx.x;
    const int wid  = tid >> 5;
    const int lane = tid & 31;
    const int b    = blockIdx.z;
    const int h0   = blockIdx.y * 4;
    const int w0   = blockIdx.x * 32;

    float* b1_s = (float*)(smem + B1S_OFF);
    float* b2_s = (float*)(smem + B2S_OFF);

    // per-thread cp.async coordinates
    const int w1row = tid >> 3, w1seg = tid & 7;     // 32 x 8
    const int w2row = tid >> 2, w2seg = tid & 3;     // 64 x 4

    // ---- pre-issue 4 groups: W1(0), W2(0), W1(1), W2(1) ----
    cp16(sb + W1_OFF + w1row * W1PB + w1seg * 16, g_w1h + w1row * 64 + w1seg * 8);
    cp_commit();
    cp16(sb + W2_OFF + w2row * W2PB + w2seg * 16, g_w2h + w2row * 256 + w2seg * 8);
    cp_commit();
    cp16(sb + W1_OFF + 4608 + w1row * W1PB + w1seg * 16,
         g_w1h + NH * 64 + w1row * 64 + w1seg * 8);
    cp_commit();
    cp16(sb + W2_OFF + 5120 + w2row * W2PB + w2seg * 16,
         g_w2h + w2row * 256 + NH + w2seg * 8);
    cp_commit();

    // ---- stage x -> fp16 [pix][c], float4 global loads ----
    for (int i = tid; i < 64 * 4 * 8; i += THREADS) {      // c(64) x r(4) x colgrp(8)
        const int c = i >> 5, r = (i >> 3) & 3, cg = i & 7;
        const float4 v = *(const float4*)&x[
            (((size_t)b * C_IN + c) * H_SZ + (h0 + r)) * W_SZ + w0 + cg * 4];
        char* dst = smem + X_OFF + (r * 32 + cg * 4) * XPB + c * 2;
        *(__half*)(dst)           = __float2half_rn(v.x);
        *(__half*)(dst + XPB)     = __float2half_rn(v.y);
        *(__half*)(dst + 2 * XPB) = __float2half_rn(v.z);
        *(__half*)(dst + 3 * XPB) = __float2half_rn(v.w);
    }
    if (tid < HID)  b1_s[tid] = b1[tid];
    if (tid < C_IN) b2_s[tid] = b2[tid];

    // ---- warp geometry ----
    const int pr  = wid & 3;              // pixel group
    const int wcg = wid >> 2;             // n group
    const int aRow = (lane & 7) + ((lane >> 3) & 1) * 8;
    const int aKof = (lane >> 4) * 8;
    const int bRow = (lane & 7) + (lane >> 4) * 8;
    const int bKof = ((lane >> 3) & 1) * 8;
    const int dRow = lane >> 2;
    const int dCol = (lane & 3) * 2;

    const uint32_t aXbase = sb + X_OFF + (uint32_t)((pr * 32 + aRow) * XPB + aKof * 2);
    const uint32_t aHbase = sb + H_OFF + (uint32_t)((pr * 32 + aRow) * HPB + aKof * 2);
    const uint32_t bW1off = (uint32_t)((wcg * 16 + bRow) * W1PB + bKof * 2);
    const uint32_t bW2off = (uint32_t)((wcg * 32 + bRow) * W2PB + bKof * 2);

    // persistent GEMM2 accumulators: 32 pix x 32 c per warp
    float acc2[2][4][4];
    #pragma unroll
    for (int mt = 0; mt < 2; ++mt)
        #pragma unroll
        for (int nt = 0; nt < 4; ++nt)
            #pragma unroll
            for (int j = 0; j < 4; ++j) acc2[mt][nt][j] = 0.f;

    // ---- 8 hid chunks of 32 ----
    #pragma unroll 1
    for (int nc = 0; nc < NCHUNK; ++nc) {
        const uint32_t w1buf = sb + W1_OFF + (nc & 1) * 4608;
        const uint32_t w2buf = sb + W2_OFF + (nc & 1) * 5120;

        // B1: W1(nc) + W2(nc) arrived; GEMM2(nc-1) retired
        if (nc == 0)                cp_wait<2>();
        else if (nc == NCHUNK - 1)  cp_wait<0>();
        else                        cp_wait<1>();
        __syncthreads();

        // issue W2(nc+1) (buffer parity freed by this B1)
        if (nc >= 1 && nc + 1 < NCHUNK) {
            cp16(sb + W2_OFF + ((nc + 1) & 1) * 5120 + w2row * W2PB + w2seg * 16,
                 g_w2h + w2row * 256 + (nc + 1) * NH + w2seg * 8);
            cp_commit();
        }

        // ===== GEMM1: [128 pix x 32 hid], K = 64, warp tile 32x16 =====
        float acc1[2][2][4];
        #pragma unroll
        for (int mt = 0; mt < 2; ++mt)
            #pragma unroll
            for (int nt = 0; nt < 2; ++nt)
                #pragma unroll
                for (int j = 0; j < 4; ++j) acc1[mt][nt][j] = 0.f;

        #pragma unroll
        for (int ks = 0; ks < 4; ++ks) {
            uint32_t ax[8], bh[4];
            LDSM4(ax[0], ax[1], ax[2], ax[3], aXbase + ks * 32);
            LDSM4(ax[4], ax[5], ax[6], ax[7], aXbase + 16 * XPB + ks * 32);
            LDSM4(bh[0], bh[1], bh[2], bh[3], w1buf + bW1off + ks * 32);
            #pragma unroll
            for (int mt = 0; mt < 2; ++mt)
                #pragma unroll
                for (int nt = 0; nt < 2; ++nt)
                    mma16816(acc1[mt][nt], ax + mt * 4, bh + nt * 2);
        }

        // ---- bias + packed-half2 GELU -> H ----
        #pragma unroll
        for (int nt = 0; nt < 2; ++nt) {
            const int nl = wcg * 16 + nt * 8 + dCol;               // 0..31
            const __half2 bias2 = __floats2half2_rn(b1_s[nc * NH + nl],
                                                    b1_s[nc * NH + nl + 1]);
            #pragma unroll
            for (int mt = 0; mt < 2; ++mt) {
                const int r0 = pr * 32 + mt * 16 + dRow;
                #pragma unroll
                for (int hh = 0; hh < 2; ++hh) {
                    *(uint32_t*)(smem + H_OFF + (r0 + hh * 8) * HPB + nl * 2) =
                        gelu2(acc1[mt][nt][hh * 2 + 0], acc1[mt][nt][hh * 2 + 1], bias2);
                }
            }
        }

        // B3: H visible; all GEMM1(nc) W1-buf reads retired
        __syncthreads();

        // issue W1(nc+2) into buf parity nc&1 (just retired by B3)
        if (nc + 2 < NCHUNK) {
            cp16(w1buf + w1row * W1PB + w1seg * 16,
                 g_w1h + (nc + 2) * NH * 64 + w1row * 64 + w1seg * 8);
            cp_commit();
        }

        // ===== GEMM2: [128 pix x 64 c] += H * W2c^T, K = 32, warp 32x32 =====
        #pragma unroll
        for (int ks = 0; ks < 2; ++ks) {
            uint32_t ah[8], bh[8];
            LDSM4(ah[0], ah[1], ah[2], ah[3], aHbase + ks * 32);
            LDSM4(ah[4], ah[5], ah[6], ah[7], aHbase + 16 * HPB + ks * 32);
            LDSM4(bh[0], bh[1], bh[2], bh[3], w2buf + bW2off + ks * 32);
            LDSM4(bh[4], bh[5], bh[6], bh[7], w2buf + bW2off + 16 * W2PB + ks * 32);
            #pragma unroll
            for (int mt = 0; mt < 2; ++mt)
                #pragma unroll
                for (int nt = 0; nt < 4; ++nt)
                    mma16816(acc2[mt][nt], ah + mt * 4, bh + nt * 2);
        }
    }

    __syncthreads();                                   // B4: all X/H/W reads done

    // ---- issue Mh copy into overlay (X/H/W1/W2/B1 regions dead) ----
    for (int i = tid; i < 2048; i += THREADS)
        cp16(sb + MH_OFF + i * 16, (const char*)g_Mh + i * 16);
    cp_commit();

    // ---- y (+b2) -> yh[c][win][k] fp16 overlay ----
    #pragma unroll
    for (int mt = 0; mt < 2; ++mt)
        #pragma unroll
        for (int nt = 0; nt < 4; ++nt) {
            const int c0 = wcg * 32 + nt * 8 + dCol;
            #pragma unroll
            for (int hh = 0; hh < 2; ++hh) {
                const int col = mt * 16 + hh * 8 + dRow;       // 0..31
                const int win = col >> 2;
                const int kk  = pr * 4 + (col & 3);            // in-patch index
                const uint32_t o = (uint32_t)(win * 32 + kk * 2);
                *(__half*)(smem + YH_OFF + c0 * 256 + o) =
                    __float2half_rn(acc2[mt][nt][hh * 2 + 0] + b2_s[c0]);
                *(__half*)(smem + YH_OFF + (c0 + 1) * 256 + o) =
                    __float2half_rn(acc2[mt][nt][hh * 2 + 1] + b2_s[c0 + 1]);
            }
        }
    cp_wait<0>();
    __syncthreads();                                   // B5: yh + Mh ready

    // ---- Fourier mix via mma: 8 channels per warp, 1 mma each ----
    const uint32_t aoff = sb + MH_OFF +
        (uint32_t)((((lane & 7) + ((lane >> 3) & 1) * 8) * 16 + ((lane >> 4) & 1) * 8) * 2);
    const uint32_t boff = sb + YH_OFF +
        (uint32_t)(((lane & 7) * 16 + ((lane >> 3) & 1) * 8) * 2);
    const int cb = wid * 8;

    #pragma unroll
    for (int j = 0; j < 8; ++j) {
        const int c = cb + j;
        uint32_t a[4], bb[2];
        LDSM4(a[0], a[1], a[2], a[3], aoff + c * 512);
        LDSM2(bb[0], bb[1], boff + c * 256);
        float d[4] = {0.f, 0.f, 0.f, 0.f};
        mma16816(d, a, bb);
        const size_t base = (((size_t)(b * C_IN + c)) * H_SZ + h0 + (dRow >> 2)) * W_SZ
                          + w0 + dCol * 4 + (dRow & 3);
        out[base]           = d[0];
        out[base + 4]       = d[1];
        out[base + 2 * 256] = d[2];
        out[base + 2 * 256 + 4] = d[3];
    }
}

// ---------------------------------------------------------------------------
extern "C" void kernel_launch(void* const* d_in, const int* in_sizes, int n_in,
                              void* d_out, int out_size) {
    const float* x  = (const float*)d_in[0];
    const float* w1 = (const float*)d_in[1];
    const float* b1 = (const float*)d_in[2];
    const float* w2 = (const float*)d_in[3];
    const float* b2 = (const float*)d_in[4];
    const float* cw = (const float*)d_in[5];
    float* out = (float*)d_out;

    cudaFuncSetAttribute(fmffn_kernel,
                         cudaFuncAttributeMaxDynamicSharedMemorySize, SMEM_BYTES);

    build_all_kernel<<<96, 256>>>(cw, w1, w2);

    dim3 grid(W_SZ / 32, H_SZ / 4, B_SZ);   // (8, 64, 8)
    fmffn_kernel<<<grid, THREADS, SMEM_BYTES>>>(x, b1, b2, out);
}